// round 16
// baseline (speedup 1.0000x reference)
#include <cuda_runtime.h>
#include <cuda_fp16.h>
#include <cstdint>

// Problem constants
#define BATCH 64
#define SEQT  512
#define IN    512
#define HID   1024
#define G4    4096
#define KTOT  1536
#define OUTD  512

#define NBLK  128           // persistent grid, 1 CTA/SM
#define NTHR  512           // 16 warps = (kslice 0..7) x (mhalf 0..1)
#define K16TOT 96           // k16 steps: x 0..31, h 32..95
#define K16X  32
#define KSL   12            // k16 per warp K-slice (96/8)

// smem: W fragment-packed fp16 (resident) + 16 partial tiles (32x32, pitch 33)
#define WF_UINTS (K16TOT * 32 * 8)         // 24576 uint32 = 98304 B
#define P_PITCH   33
#define P_TILE    (32 * P_PITCH)
#define SMEM_TOTAL (WF_UINTS * 4 + 16 * P_TILE * 4)   // 165888 B

// ---- device-global scratch ----
__device__ float    d_W[(size_t)G4 * KTOT];              // fp32 packed cols
__device__ float    d_bias[G4];
// x in fp16 A-fragment order: [t][k16][mt][lane][reg(4)x half(2)]
__device__ __half   d_xfrag[(size_t)SEQT * K16X * 4 * 32 * 8];
// h in fp16 A-fragment order, double buffered: [buf][k16h(64)][mt][lane][8]
__device__ __half   d_hfrag[2 * 64 * 4 * 32 * 8];
__device__ float    d_hfin[BATCH * HID];
__device__ unsigned d_bar_grp[8 * 64];                   // spread group counters
__device__ unsigned d_bar_root;

// ============================ helpers =======================================
__device__ __forceinline__ void mma_f16(float c[4], const uint32_t a[4],
                                        const uint32_t b[2]) {
    asm volatile(
        "mma.sync.aligned.m16n8k16.row.col.f32.f16.f16.f32 "
        "{%0,%1,%2,%3}, {%4,%5,%6,%7}, {%8,%9}, {%0,%1,%2,%3};"
        : "+f"(c[0]), "+f"(c[1]), "+f"(c[2]), "+f"(c[3])
        : "r"(a[0]), "r"(a[1]), "r"(a[2]), "r"(a[3]), "r"(b[0]), "r"(b[1]));
}
__device__ __forceinline__ float sigf(float v)     { return 1.f / (1.f + __expf(-v)); }
__device__ __forceinline__ float tanhfast(float v) { return 2.f / (1.f + __expf(-2.f * v)) - 1.f; }

// ============================ prep kernel ===================================
// Packed W column j: gate g=(j>>3)&3 (f,i,c,o), unit=(j>>5)*8+(j&7).
// x fragments (m16n8k16 A): element (half,reg,lane,mt,k16,t):
//   b = mt*16 + (lane>>2) + 8*(reg&1)
//   k = k16*16 + 2*(lane&3) + half + 8*(reg>>1)
__global__ void prep_kernel(
    const float* __restrict__ x,
    const float* __restrict__ Wxf, const float* __restrict__ Whf, const float* __restrict__ bhf,
    const float* __restrict__ Wxi, const float* __restrict__ Whi, const float* __restrict__ bhi,
    const float* __restrict__ Wxc, const float* __restrict__ Whc, const float* __restrict__ bhc,
    const float* __restrict__ Wxo, const float* __restrict__ Who, const float* __restrict__ bho)
{
    const float* Wx[4] = {Wxf, Wxi, Wxc, Wxo};
    const float* Wh[4] = {Whf, Whi, Whc, Who};
    const float* bh[4] = {bhf, bhi, bhc, bho};

    size_t gid = (size_t)blockIdx.x * blockDim.x + threadIdx.x;
    size_t str = (size_t)gridDim.x * blockDim.x;

    for (size_t i = gid; i < (size_t)G4 * KTOT; i += str) {
        int j = (int)(i / KTOT), k = (int)(i % KTOT);
        int g = (j >> 3) & 3;
        int r = (j >> 5) * 8 + (j & 7);
        d_W[i] = (k < IN) ? Wx[g][(size_t)r * IN + k]
                          : Wh[g][(size_t)r * HID + (k - IN)];
    }
    for (size_t i = gid; i < (size_t)G4; i += str) {
        int g = (int)((i >> 3) & 3);
        int r = (int)((i >> 5) * 8 + (i & 7));
        d_bias[i] = bh[g][r];
    }
    for (size_t i = gid; i < (size_t)SEQT * K16X * 4 * 32 * 8; i += str) {
        int half = (int)(i & 1);
        int reg  = (int)((i >> 1) & 3);
        int lane = (int)((i >> 3) & 31);
        int mt   = (int)((i >> 8) & 3);
        int k16  = (int)((i >> 10) & 31);
        int t    = (int)(i >> 15);
        int b = mt * 16 + (lane >> 2) + 8 * (reg & 1);
        int k = k16 * 16 + 2 * (lane & 3) + half + 8 * (reg >> 1);
        d_xfrag[i] = __float2half_rn(x[((size_t)b * SEQT + t) * IN + k]);
    }
    for (size_t i = gid; i < (size_t)(2 * 64 * 4 * 32 * 8) / 2; i += str)
        ((uint32_t*)d_hfrag)[i] = 0u;
    for (size_t i = gid; i < 8 * 64; i += str) d_bar_grp[i] = 0u;
    if (gid == 0) d_bar_root = 0u;
}

// ============================ fragment loads ================================
// A-fragment load: one LDG.128 (8 fp16 = K16 x row-pair), coalesced
__device__ __forceinline__ uint4 ldA(int t, int rbuf, int k16, int mt, int lane)
{
    if (k16 < K16X) {
        size_t idx = (((size_t)t * K16X + k16) * 4 + mt) * 32 + lane;
        return __ldg((const uint4*)d_xfrag + idx);
    } else {
        size_t idx = ((size_t)(rbuf * 64 + (k16 - K16X)) * 4 + mt) * 32 + lane;
        return __ldcg((const uint4*)d_hfrag + idx);
    }
}
// B fragments for one k16: 2 x LDS.128 (8 b32 = 4 nt x 2 regs)
__device__ __forceinline__ void ldB(const uint32_t* Wf, int k16, int lane, uint32_t bfr[4][2])
{
    const uint4* p = (const uint4*)&Wf[(size_t)(k16 * 32 + lane) * 8];
    uint4 w0 = p[0], w1 = p[1];
    bfr[0][0] = w0.x; bfr[0][1] = w0.y;
    bfr[1][0] = w0.z; bfr[1][1] = w0.w;
    bfr[2][0] = w1.x; bfr[2][1] = w1.y;
    bfr[3][0] = w1.z; bfr[3][1] = w1.w;
}

// ============================ main persistent kernel ========================
__global__ void __launch_bounds__(NTHR, 1) lstm_kernel(
    const float* __restrict__ Wout,
    const float* __restrict__ bout,
    float* __restrict__ out)
{
    extern __shared__ uint32_t smu[];
    uint32_t* Wf = smu;                       // fp16 fragment-packed weights
    float*    P  = (float*)(smu + WF_UINTS);  // 16 partial tiles

    const int tid  = threadIdx.x;
    const int wid  = tid >> 5;
    const int lane = tid & 31;
    const int g8   = lane >> 2;
    const int ql   = lane & 3;
    const int blk  = blockIdx.x;

    const int kslice = wid >> 1;          // 0..7
    const int mhalf  = wid & 1;           // batch half
    const int k16base = kslice * KSL;
    const int mbase  = mhalf * 2;         // mt in {mbase, mbase+1}
    const bool pre_ok = (k16base + 2 < K16X);   // first 3 prefetch k16s are x

    // ---- one-time: pack W cols into fp16 B-fragment order (2xLDS.128/k16) --
    for (int j = tid; j < K16TOT * 32; j += NTHR) {
        int k16 = j >> 5, ln = j & 31;
#pragma unroll
        for (int nt = 0; nt < 4; nt++) {
            size_t col = (size_t)(blk * 32 + nt * 8 + (ln >> 2));
#pragma unroll
            for (int reg = 0; reg < 2; reg++) {
                int k0 = k16 * 16 + reg * 8 + 2 * (ln & 3);
                __half2 h2 = __floats2half2_rn(__ldg(&d_W[col * KTOT + k0]),
                                               __ldg(&d_W[col * KTOT + k0 + 1]));
                Wf[(size_t)j * 8 + nt * 2 + reg] = *(uint32_t*)&h2;
            }
        }
    }
    __syncthreads();

    // ---- epilogue persistent state: each thread owns ONE (b,u) pair ----
    const int bp = tid >> 3, up = tid & 7;
    float cst = 0.f;
    float bias[4];
#pragma unroll
    for (int g = 0; g < 4; g++)
        bias[g] = __ldg(&d_bias[blk * 32 + g * 8 + up]);

    // precomputed h-fragment store index pieces (unit ug = blk*8+up, batch bp)
    const int ug    = blk * 8 + up;
    const int k16h  = ug >> 4;
    const int ku    = ug & 15;
    const int hmt   = bp >> 4;
    const int hrow  = bp & 15;
    const int hlane = (hrow & 7) * 4 + ((ku & 7) >> 1);
    const int hreg  = ((hrow >> 3) & 1) | ((ku >> 3) << 1);
    const int hhalf = ku & 1;

    for (int t = 0; t < SEQT; t++) {
        const int rbuf = t & 1, wbuf = rbuf ^ 1;

        float acc[2][4][4];
#pragma unroll
        for (int m2 = 0; m2 < 2; m2++)
#pragma unroll
            for (int nt = 0; nt < 4; nt++)
#pragma unroll
                for (int c = 0; c < 4; c++) acc[m2][nt][c] = 0.f;

        // x-region prefetch is barrier-independent: issue before the wait
        uint4 apf[3][2];
        if (pre_ok) {
#pragma unroll
            for (int d = 0; d < 3; d++)
#pragma unroll
                for (int m2 = 0; m2 < 2; m2++)
                    apf[d][m2] = ldA(t, rbuf, k16base + d, mbase + m2, lane);
        }

        // -------- CTA-wide wait for peers' h(t-1) --------
        // (this sync also protects P tiles: previous step's reduce reads are
        //  done before this step's merge stores)
        if (t > 0) {
            if (tid == 0) {
                while (*(volatile unsigned*)&d_bar_root < 8u * (unsigned)t)
                    __nanosleep(32);
                __threadfence();
            }
            __syncthreads();
        }
        if (!pre_ok) {
#pragma unroll
            for (int d = 0; d < 3; d++)
#pragma unroll
                for (int m2 = 0; m2 < 2; m2++)
                    apf[d][m2] = ldA(t, rbuf, k16base + d, mbase + m2, lane);
        }

        // -------- MMA phase: M=32 x N=32, K=192 per warp (12 k16), no syncs
#pragma unroll 3
        for (int j = 0; j < KSL; j++) {
            const int slot = j % 3;
            uint32_t bfr[4][2];
            ldB(Wf, k16base + j, lane, bfr);
#pragma unroll
            for (int m2 = 0; m2 < 2; m2++)
#pragma unroll
                for (int nt = 0; nt < 4; nt++)
                    mma_f16(acc[m2][nt], (const uint32_t*)&apf[slot][m2], bfr[nt]);
            if (j + 3 < KSL) {
#pragma unroll
                for (int m2 = 0; m2 < 2; m2++)
                    apf[slot][m2] = ldA(t, rbuf, k16base + j + 3, mbase + m2, lane);
            }
        }

        // -------- single-phase merge: each warp stores its OWN tile --------
        {
            float* Pw = P + wid * P_TILE;
#pragma unroll
            for (int m2 = 0; m2 < 2; m2++)
#pragma unroll
                for (int nt = 0; nt < 4; nt++)
#pragma unroll
                    for (int c = 0; c < 4; c++) {
                        int row = m2 * 16 + g8 + 8 * (c >> 1);
                        int col = nt * 8 + 2 * ql + (c & 1);
                        Pw[row * P_PITCH + col] = acc[m2][nt][c];
                    }
        }
        __syncthreads();

        // -------- reduction over 8 kslice tiles + gate fusion --------
        {
            const int mh = bp >> 5, r = bp & 31;
            float pa[4];
#pragma unroll
            for (int g = 0; g < 4; g++) {
                float s = bias[g];
#pragma unroll
                for (int ks = 0; ks < 8; ks++)
                    s += P[(ks * 2 + mh) * P_TILE + r * P_PITCH + g * 8 + up];
                pa[g] = s;
            }
            float f = sigf(pa[0]), ig = sigf(pa[1]);
            float ch = tanhfast(pa[2]), o = sigf(pa[3]);
            cst = f * cst + ig * ch;
            float hv = o * tanhfast(cst);
            if (t < SEQT - 1) {
                size_t idx = ((((size_t)(wbuf * 64 + k16h) * 4 + hmt) * 32 + hlane) * 4
                              + hreg) * 2 + hhalf;
                d_hfrag[idx] = __float2half_rn(hv);
            } else {
                d_hfin[bp * HID + ug] = hv;
            }
        }

        // -------- per-warp arrival (no CTA-wide sync) --------
        __syncwarp();
        if (lane == 0) {
            __threadfence();
            const unsigned grp = (unsigned)(blk >> 4);   // 16 CTAs x 16 warps
            unsigned v = atomicAdd(&d_bar_grp[grp * 64], 1u) + 1u;
            if (v == 256u * (unsigned)(t + 1))
                atomicAdd(&d_bar_root, 1u);
        }
    }

    // final wait: all CTAs' last h written before the tail GEMM
    if (tid == 0) {
        while (*(volatile unsigned*)&d_bar_root < 8u * (unsigned)SEQT)
            __nanosleep(32);
        __threadfence();
    }
    __syncthreads();

    // ---- tail: out[b][o] = h_final[b] . Wout[o] + bout[o]
    if (tid < 256) {
        const int gtid = blk * 256 + tid;
        const int b = gtid & 63, o = gtid >> 6;
        const float4* hr = (const float4*)&d_hfin[(size_t)b * HID];
        const float4* wr = (const float4*)(Wout + ((size_t)o << 10));
        float s = __ldg(&bout[o]);
#pragma unroll 4
        for (int k = 0; k < HID / 4; k++) {
            float4 h4 = __ldcg(hr + k);
            float4 w4 = __ldg(wr + k);
            s += h4.x * w4.x + h4.y * w4.y + h4.z * w4.z + h4.w * w4.w;
        }
        out[(size_t)b * OUTD + o] = s;
    }
}

// ============================================================================
extern "C" void kernel_launch(void* const* d_in, const int* in_sizes, int n_in,
                              void* d_out, int out_size)
{
    (void)in_sizes; (void)n_in; (void)out_size;
    const float* x    = (const float*)d_in[0];
    const float* Wxf  = (const float*)d_in[1];
    const float* Whf  = (const float*)d_in[2];
    const float* bhf  = (const float*)d_in[3];
    const float* Wxi  = (const float*)d_in[4];
    const float* Whi  = (const float*)d_in[5];
    const float* bhi  = (const float*)d_in[6];
    const float* Wxc  = (const float*)d_in[7];
    const float* Whc  = (const float*)d_in[8];
    const float* bhc  = (const float*)d_in[9];
    const float* Wxo  = (const float*)d_in[10];
    const float* Who  = (const float*)d_in[11];
    const float* bho  = (const float*)d_in[12];
    const float* Wout = (const float*)d_in[13];
    const float* bout = (const float*)d_in[14];
    float* out = (float*)d_out;

    cudaFuncSetAttribute(lstm_kernel,
                         cudaFuncAttributeMaxDynamicSharedMemorySize, SMEM_TOTAL);

    prep_kernel<<<2048, 256>>>(x, Wxf, Whf, bhf, Wxi, Whi, bhi,
                               Wxc, Whc, bhc, Wxo, Who, bho);
    lstm_kernel<<<NBLK, NTHR, SMEM_TOTAL>>>(Wout, bout, out);
}

// round 17
// speedup vs baseline: 1.4463x; 1.4463x over previous
#include <cuda_runtime.h>
#include <cuda_fp16.h>
#include <cstdint>

// Problem constants
#define BATCH 64
#define SEQT  512
#define IN    512
#define HID   1024
#define G4    4096
#define KTOT  1536
#define OUTD  512

#define NBLK  128           // persistent grid, 1 CTA/SM
#define NTHR  512           // 16 warps = (kslice 0..7) x (mhalf 0..1)
#define K16TOT 96           // k16 steps: x 0..31, h 32..95
#define K16X  32
#define XSL   4             // x k16 per kslice
#define HSL   8             // h k16 per kslice

// smem: W fragment-packed fp16 (resident) + 8 merged partial tiles (32x32)
#define WF_UINTS (K16TOT * 32 * 8)         // 24576 uint32 = 98304 B
#define P_PITCH   40
#define P_TILE    (32 * P_PITCH)
#define SMEM_TOTAL (WF_UINTS * 4 + 8 * P_TILE * 4)   // 139264 B

// ---- device-global scratch ----
__device__ float    d_W[(size_t)G4 * KTOT];              // fp32 packed cols
__device__ float    d_bias[G4];
// x in fp16 A-fragment order: [t][k16][mt][lane][reg(4)x half(2)]
__device__ __half   d_xfrag[(size_t)SEQT * K16X * 4 * 32 * 8];
// h in fp16 A-fragment order, double buffered: [buf][k16h(64)][mt][lane][8]
__device__ __half   d_hfrag[2 * 64 * 4 * 32 * 8];
__device__ float    d_hfin[BATCH * HID];
__device__ unsigned d_bar_grp[8 * 64];                   // spread group counters
__device__ unsigned d_bar_root;

// ============================ helpers =======================================
__device__ __forceinline__ void mma_f16(float c[4], const uint32_t a[4],
                                        const uint32_t b[2]) {
    asm volatile(
        "mma.sync.aligned.m16n8k16.row.col.f32.f16.f16.f32 "
        "{%0,%1,%2,%3}, {%4,%5,%6,%7}, {%8,%9}, {%0,%1,%2,%3};"
        : "+f"(c[0]), "+f"(c[1]), "+f"(c[2]), "+f"(c[3])
        : "r"(a[0]), "r"(a[1]), "r"(a[2]), "r"(a[3]), "r"(b[0]), "r"(b[1]));
}
__device__ __forceinline__ float sigf(float v)     { return 1.f / (1.f + __expf(-v)); }
__device__ __forceinline__ float tanhfast(float v) { return 2.f / (1.f + __expf(-2.f * v)) - 1.f; }

// ============================ prep kernel ===================================
// Packed W column j: gate g=(j>>3)&3 (f,i,c,o), unit=(j>>5)*8+(j&7).
// x fragments (m16n8k16 A): element (half,reg,lane,mt,k16,t):
//   b = mt*16 + (lane>>2) + 8*(reg&1)
//   k = k16*16 + 2*(lane&3) + half + 8*(reg>>1)
__global__ void prep_kernel(
    const float* __restrict__ x,
    const float* __restrict__ Wxf, const float* __restrict__ Whf, const float* __restrict__ bhf,
    const float* __restrict__ Wxi, const float* __restrict__ Whi, const float* __restrict__ bhi,
    const float* __restrict__ Wxc, const float* __restrict__ Whc, const float* __restrict__ bhc,
    const float* __restrict__ Wxo, const float* __restrict__ Who, const float* __restrict__ bho)
{
    const float* Wx[4] = {Wxf, Wxi, Wxc, Wxo};
    const float* Wh[4] = {Whf, Whi, Whc, Who};
    const float* bh[4] = {bhf, bhi, bhc, bho};

    size_t gid = (size_t)blockIdx.x * blockDim.x + threadIdx.x;
    size_t str = (size_t)gridDim.x * blockDim.x;

    for (size_t i = gid; i < (size_t)G4 * KTOT; i += str) {
        int j = (int)(i / KTOT), k = (int)(i % KTOT);
        int g = (j >> 3) & 3;
        int r = (j >> 5) * 8 + (j & 7);
        d_W[i] = (k < IN) ? Wx[g][(size_t)r * IN + k]
                          : Wh[g][(size_t)r * HID + (k - IN)];
    }
    for (size_t i = gid; i < (size_t)G4; i += str) {
        int g = (int)((i >> 3) & 3);
        int r = (int)((i >> 5) * 8 + (i & 7));
        d_bias[i] = bh[g][r];
    }
    for (size_t i = gid; i < (size_t)SEQT * K16X * 4 * 32 * 8; i += str) {
        int half = (int)(i & 1);
        int reg  = (int)((i >> 1) & 3);
        int lane = (int)((i >> 3) & 31);
        int mt   = (int)((i >> 8) & 3);
        int k16  = (int)((i >> 10) & 31);
        int t    = (int)(i >> 15);
        int b = mt * 16 + (lane >> 2) + 8 * (reg & 1);
        int k = k16 * 16 + 2 * (lane & 3) + half + 8 * (reg >> 1);
        d_xfrag[i] = __float2half_rn(x[((size_t)b * SEQT + t) * IN + k]);
    }
    for (size_t i = gid; i < (size_t)(2 * 64 * 4 * 32 * 8) / 2; i += str)
        ((uint32_t*)d_hfrag)[i] = 0u;
    for (size_t i = gid; i < 8 * 64; i += str) d_bar_grp[i] = 0u;
    if (gid == 0) d_bar_root = 0u;
}

// ============================ fragment loads ================================
__device__ __forceinline__ uint4 ldX16(int t, int k16, int mt, int lane)
{
    size_t idx = (((size_t)t * K16X + k16) * 4 + mt) * 32 + lane;
    return __ldg((const uint4*)d_xfrag + idx);
}
__device__ __forceinline__ uint4 ldH16(int rbuf, int k16h, int mt, int lane)
{
    size_t idx = ((size_t)(rbuf * 64 + k16h) * 4 + mt) * 32 + lane;
    return __ldcg((const uint4*)d_hfrag + idx);
}
// B fragments for one k16: 2 x LDS.128 (8 b32 = 4 nt x 2 regs)
__device__ __forceinline__ void ldB(const uint32_t* Wf, int k16, int lane, uint32_t bfr[4][2])
{
    const uint4* p = (const uint4*)&Wf[(size_t)(k16 * 32 + lane) * 8];
    uint4 w0 = p[0], w1 = p[1];
    bfr[0][0] = w0.x; bfr[0][1] = w0.y;
    bfr[1][0] = w0.z; bfr[1][1] = w0.w;
    bfr[2][0] = w1.x; bfr[2][1] = w1.y;
    bfr[3][0] = w1.z; bfr[3][1] = w1.w;
}

// ============================ main persistent kernel ========================
__global__ void __launch_bounds__(NTHR, 1) lstm_kernel(
    const float* __restrict__ Wout,
    const float* __restrict__ bout,
    float* __restrict__ out)
{
    extern __shared__ uint32_t smu[];
    uint32_t* Wf = smu;                       // fp16 fragment-packed weights
    float*    P  = (float*)(smu + WF_UINTS);  // 8 merged partial tiles

    const int tid  = threadIdx.x;
    const int wid  = tid >> 5;
    const int lane = tid & 31;
    const int g8   = lane >> 2;
    const int ql   = lane & 3;
    const int blk  = blockIdx.x;

    const int kslice = wid >> 1;          // 0..7
    const int mhalf  = wid & 1;           // batch half
    const int mbase  = mhalf * 2;         // mt in {mbase, mbase+1}
    const int xk0    = kslice * XSL;      // x k16 base (0..28)
    const int hk0    = kslice * HSL;      // h k16h base (0..56)

    // ---- one-time: pack W cols into fp16 B-fragment order (2xLDS.128/k16) --
    for (int j = tid; j < K16TOT * 32; j += NTHR) {
        int k16 = j >> 5, ln = j & 31;
#pragma unroll
        for (int nt = 0; nt < 4; nt++) {
            size_t col = (size_t)(blk * 32 + nt * 8 + (ln >> 2));
#pragma unroll
            for (int reg = 0; reg < 2; reg++) {
                int k0 = k16 * 16 + reg * 8 + 2 * (ln & 3);
                __half2 h2 = __floats2half2_rn(__ldg(&d_W[col * KTOT + k0]),
                                               __ldg(&d_W[col * KTOT + k0 + 1]));
                Wf[(size_t)j * 8 + nt * 2 + reg] = *(uint32_t*)&h2;
            }
        }
    }
    __syncthreads();

    // ---- epilogue persistent state: each thread owns ONE (b,u) pair ----
    const int bp = tid >> 3, up = tid & 7;
    float cst = 0.f;
    float bias[4];
#pragma unroll
    for (int g = 0; g < 4; g++)
        bias[g] = __ldg(&d_bias[blk * 32 + g * 8 + up]);

    // precomputed h-fragment store index pieces (unit ug = blk*8+up, batch bp)
    const int ug    = blk * 8 + up;
    const int k16h  = ug >> 4;
    const int ku    = ug & 15;
    const int hmt   = bp >> 4;
    const int hrow  = bp & 15;
    const int hlane = (hrow & 7) * 4 + ((ku & 7) >> 1);
    const int hreg  = ((hrow >> 3) & 1) | ((ku >> 3) << 1);
    const int hhalf = ku & 1;

    for (int t = 0; t < SEQT; t++) {
        const int rbuf = t & 1, wbuf = rbuf ^ 1;

        float acc[2][4][4];
#pragma unroll
        for (int m2 = 0; m2 < 2; m2++)
#pragma unroll
            for (int nt = 0; nt < 4; nt++)
#pragma unroll
                for (int c = 0; c < 4; c++) acc[m2][nt][c] = 0.f;

        uint32_t bfr[2][4][2];

        // ============ x-phase: 4 k16, barrier-independent ============
        {
            uint4 apx[2][2];
#pragma unroll
            for (int d = 0; d < 2; d++)
#pragma unroll
                for (int m2 = 0; m2 < 2; m2++)
                    apx[d][m2] = ldX16(t, xk0 + d, mbase + m2, lane);
            ldB(Wf, xk0, lane, bfr[0]);
#pragma unroll
            for (int j = 0; j < XSL; j++) {
                const int slot = j & 1;
                if (j + 1 < XSL) ldB(Wf, xk0 + j + 1, lane, bfr[(j + 1) & 1]);
#pragma unroll
                for (int m2 = 0; m2 < 2; m2++)
#pragma unroll
                    for (int nt = 0; nt < 4; nt++)
                        mma_f16(acc[m2][nt], (const uint32_t*)&apx[slot][m2], bfr[slot][nt]);
                if (j + 2 < XSL) {
#pragma unroll
                    for (int m2 = 0; m2 < 2; m2++)
                        apx[slot][m2] = ldX16(t, xk0 + j + 2, mbase + m2, lane);
                }
            }
        }

        // ============ CTA-wide wait for peers' h(t-1) ============
        if (t > 0) {
            if (tid == 0) {
                while (*(volatile unsigned*)&d_bar_root < 8u * (unsigned)t)
                    __nanosleep(32);
                __threadfence();
            }
            __syncthreads();
        }

        // ============ h-phase: 8 k16 ============
        {
            uint4 aph[3][2];
#pragma unroll
            for (int d = 0; d < 3; d++)
#pragma unroll
                for (int m2 = 0; m2 < 2; m2++)
                    aph[d][m2] = ldH16(rbuf, hk0 + d, mbase + m2, lane);
            ldB(Wf, K16X + hk0, lane, bfr[0]);
#pragma unroll
            for (int j = 0; j < HSL; j++) {
                const int slot = j % 3;
                if (j + 1 < HSL) ldB(Wf, K16X + hk0 + j + 1, lane, bfr[(j + 1) & 1]);
#pragma unroll
                for (int m2 = 0; m2 < 2; m2++)
#pragma unroll
                    for (int nt = 0; nt < 4; nt++)
                        mma_f16(acc[m2][nt], (const uint32_t*)&aph[slot][m2], bfr[j & 1][nt]);
                if (j + 3 < HSL) {
#pragma unroll
                    for (int m2 = 0; m2 < 2; m2++)
                        aph[slot][m2] = ldH16(rbuf, hk0 + j + 3, mbase + m2, lane);
                }
            }
        }

        // -------- two-phase partial merge into 8 tiles (float2 stores) -----
        float* Pw = P + (wid & 7) * P_TILE;
        if (wid < 8) {
#pragma unroll
            for (int m2 = 0; m2 < 2; m2++)
#pragma unroll
                for (int nt = 0; nt < 4; nt++)
#pragma unroll
                    for (int ch = 0; ch < 2; ch++) {
                        int row = m2 * 16 + g8 + 8 * ch;
                        int col = nt * 8 + 2 * ql;
                        *(float2*)&Pw[row * P_PITCH + col] =
                            make_float2(acc[m2][nt][2 * ch], acc[m2][nt][2 * ch + 1]);
                    }
        }
        __syncthreads();
        if (wid >= 8) {
#pragma unroll
            for (int m2 = 0; m2 < 2; m2++)
#pragma unroll
                for (int nt = 0; nt < 4; nt++)
#pragma unroll
                    for (int ch = 0; ch < 2; ch++) {
                        int row = m2 * 16 + g8 + 8 * ch;
                        int col = nt * 8 + 2 * ql;
                        float2 v = *(const float2*)&Pw[row * P_PITCH + col];
                        v.x += acc[m2][nt][2 * ch];
                        v.y += acc[m2][nt][2 * ch + 1];
                        *(float2*)&Pw[row * P_PITCH + col] = v;
                    }
        }
        __syncthreads();

        // -------- reduction + gate fusion (1 pair per thread) --------
        {
            const int mh = bp >> 5, r = bp & 31;
            float pa[4];
#pragma unroll
            for (int g = 0; g < 4; g++) {
                float s = bias[g];
#pragma unroll
                for (int ks = 0; ks < 4; ks++)
                    s += P[(ks * 2 + mh) * P_TILE + r * P_PITCH + g * 8 + up];
                pa[g] = s;
            }
            float f = sigf(pa[0]), ig = sigf(pa[1]);
            float ch = tanhfast(pa[2]), o = sigf(pa[3]);
            cst = f * cst + ig * ch;
            float hv = o * tanhfast(cst);
            if (t < SEQT - 1) {
                size_t idx = ((((size_t)(wbuf * 64 + k16h) * 4 + hmt) * 32 + hlane) * 4
                              + hreg) * 2 + hhalf;
                d_hfrag[idx] = __float2half_rn(hv);
            } else {
                d_hfin[bp * HID + ug] = hv;
            }
        }

        // -------- arrive (release h(t)) --------
        __syncthreads();
        if (tid == 0) {
            __threadfence();
            const unsigned grp = (unsigned)(blk >> 4);
            unsigned v = atomicAdd(&d_bar_grp[grp * 64], 1u) + 1u;
            if (v == 16u * (unsigned)(t + 1))
                atomicAdd(&d_bar_root, 1u);
        }
    }

    // final wait: all CTAs' last h written before the tail GEMM
    if (tid == 0) {
        while (*(volatile unsigned*)&d_bar_root < 8u * (unsigned)SEQT)
            __nanosleep(32);
        __threadfence();
    }
    __syncthreads();

    // ---- tail: out[b][o] = h_final[b] . Wout[o] + bout[o]
    if (tid < 256) {
        const int gtid = blk * 256 + tid;
        const int b = gtid & 63, o = gtid >> 6;
        const float4* hr = (const float4*)&d_hfin[(size_t)b * HID];
        const float4* wr = (const float4*)(Wout + ((size_t)o << 10));
        float s = __ldg(&bout[o]);
#pragma unroll 4
        for (int k = 0; k < HID / 4; k++) {
            float4 h4 = __ldcg(hr + k);
            float4 w4 = __ldg(wr + k);
            s += h4.x * w4.x + h4.y * w4.y + h4.z * w4.z + h4.w * w4.w;
        }
        out[(size_t)b * OUTD + o] = s;
    }
}

// ============================================================================
extern "C" void kernel_launch(void* const* d_in, const int* in_sizes, int n_in,
                              void* d_out, int out_size)
{
    (void)in_sizes; (void)n_in; (void)out_size;
    const float* x    = (const float*)d_in[0];
    const float* Wxf  = (const float*)d_in[1];
    const float* Whf  = (const float*)d_in[2];
    const float* bhf  = (const float*)d_in[3];
    const float* Wxi  = (const float*)d_in[4];
    const float* Whi  = (const float*)d_in[5];
    const float* bhi  = (const float*)d_in[6];
    const float* Wxc  = (const float*)d_in[7];
    const float* Whc  = (const float*)d_in[8];
    const float* bhc  = (const float*)d_in[9];
    const float* Wxo  = (const float*)d_in[10];
    const float* Who  = (const float*)d_in[11];
    const float* bho  = (const float*)d_in[12];
    const float* Wout = (const float*)d_in[13];
    const float* bout = (const float*)d_in[14];
    float* out = (float*)d_out;

    cudaFuncSetAttribute(lstm_kernel,
                         cudaFuncAttributeMaxDynamicSharedMemorySize, SMEM_TOTAL);

    prep_kernel<<<2048, 256>>>(x, Wxf, Whf, bhf, Wxi, Whi, bhi,
                               Wxc, Whc, bhc, Wxo, Who, bho);
    lstm_kernel<<<NBLK, NTHR, SMEM_TOTAL>>>(Wout, bout, out);
}